// round 4
// baseline (speedup 1.0000x reference)
#include <cuda_runtime.h>
#include <math.h>

// Problem constants (fixed by the dataset): B=256, K=512, D=1024
#define B_SZ 256
#define K_SZ 512
#define D_SZ 1024
#define INV_T (1.0f / 0.07f)

#define K_PER_BLOCK 8                      // 8 warps per block, one k per warp
#define BLOCKS_PER_B (K_SZ / K_PER_BLOCK)  // 64
#define NBLK (B_SZ * BLOCKS_PER_B)         // 16384

// Scratch (no cudaMalloc allowed)
__device__ float g_fg_per_b[B_SZ];         // exp(fg_logit / T) per sample
__device__ float g_part[NBLK];             // per-block partial sums
__device__ unsigned int g_count;           // arrival counter (zero-init, self-resetting)

// ---------------------------------------------------------------------------
// Single fused kernel:
//  - per-block img-row normalization (redundant 64x/row, L2 hits)
//  - 8 warps each stream one pro row from DRAM, dot vs smem img row
//  - kgrp==0 blocks also compute the fg dot
//  - LAST arriving block performs the deterministic final reduce + writes loss
// grid = 16384, block = 256 (8 warps)
// ---------------------------------------------------------------------------
__global__ void __launch_bounds__(256) fused_kernel(
    const float* __restrict__ img,
    const float* __restrict__ fg,
    const float* __restrict__ pro,
    float* __restrict__ out)
{
    __shared__ float4 s_img[256];   // 4 KB: the img row
    __shared__ float  s_ss[8];
    __shared__ float  s_fg[8];
    __shared__ float  s_part[8];
    __shared__ int    s_last;

    const int blk  = blockIdx.x;
    const int b    = blk >> 6;          // blk / BLOCKS_PER_B
    const int kgrp = blk & 63;          // blk % BLOCKS_PER_B
    const int t    = threadIdx.x;
    const int w    = t >> 5;
    const int l    = t & 31;

    // ---- load img row into smem + sum of squares ----
    float4 v = ((const float4*)(img + (size_t)b * D_SZ))[t];
    s_img[t] = v;

    float ss = v.x * v.x + v.y * v.y + v.z * v.z + v.w * v.w;
    #pragma unroll
    for (int o = 16; o > 0; o >>= 1)
        ss += __shfl_xor_sync(0xFFFFFFFFu, ss, o);
    if (l == 0) s_ss[w] = ss;
    __syncthreads();

    float tss = 0.f;
    #pragma unroll
    for (int i = 0; i < 8; i++) tss += s_ss[i];
    const float inv = 1.0f / sqrtf(tss);

    // ---- fg dot: only in the first block of each sample ----
    if (kgrp == 0) {
        float4 f = ((const float4*)(fg + (size_t)b * D_SZ))[t];
        float fd = v.x * f.x + v.y * f.y + v.z * f.z + v.w * f.w;
        #pragma unroll
        for (int o = 16; o > 0; o >>= 1)
            fd += __shfl_xor_sync(0xFFFFFFFFu, fd, o);
        if (l == 0) s_fg[w] = fd;
        __syncthreads();
        if (t == 0) {
            float tfd = 0.f;
            #pragma unroll
            for (int i = 0; i < 8; i++) tfd += s_fg[i];
            g_fg_per_b[b] = expf(tfd * inv * INV_T);
        }
    }

    // ---- each warp: one (b,k) dot, pro streamed from DRAM ----
    const int k = (kgrp << 3) + w;
    const float4* p4 = (const float4*)(pro + ((size_t)b * K_SZ + k) * D_SZ);

    float4 p[8];
    #pragma unroll
    for (int j = 0; j < 8; j++)
        p[j] = __ldcs(p4 + j * 32 + l);   // front-batched streaming loads

    float acc = 0.f;
    #pragma unroll
    for (int j = 0; j < 8; j++) {
        float4 a = s_img[j * 32 + l];
        acc += a.x * p[j].x + a.y * p[j].y + a.z * p[j].z + a.w * p[j].w;
    }

    #pragma unroll
    for (int o = 16; o > 0; o >>= 1)
        acc += __shfl_xor_sync(0xFFFFFFFFu, acc, o);
    if (l == 0) s_part[w] = expf(acc * inv * INV_T);
    __syncthreads();

    // ---- publish partial, arrive at counter; detect last block ----
    if (t == 0) {
        float tsum = 0.f;
        #pragma unroll
        for (int i = 0; i < 8; i++) tsum += s_part[i];
        g_part[blk] = tsum;
        __threadfence();                         // make partial + fg visible
        unsigned r = atomicAdd(&g_count, 1u);
        s_last = (r == (unsigned)(NBLK - 1));
    }
    __syncthreads();
    if (!s_last) return;

    // =======================================================================
    // Final deterministic reduce — executed by exactly one block, all
    // partials L2-hot. Fixed read order -> replay-deterministic.
    // =======================================================================
    if (t == 0) g_count = 0;                     // reset for next graph replay

    const float4* gp4 = (const float4*)g_part;   // 4096 float4
    double acc2 = 0.0;
    #pragma unroll
    for (int j = 0; j < 16; j++) {               // 16 independent loads/thread
        float4 x = gp4[t + j * 256];
        acc2 += ((double)x.x + (double)x.y) + ((double)x.z + (double)x.w);
    }
    double fgd = (double)g_fg_per_b[t];          // t in [0,256)

    #pragma unroll
    for (int o = 16; o > 0; o >>= 1) {
        acc2 += __shfl_xor_sync(0xFFFFFFFFu, acc2, o);
        fgd  += __shfl_xor_sync(0xFFFFFFFFu, fgd,  o);
    }

    __shared__ double sa[8];
    __shared__ double sfd[8];
    if (l == 0) { sa[w] = acc2; sfd[w] = fgd; }
    __syncthreads();

    if (t == 0) {
        double a = 0.0, f = 0.0;
        #pragma unroll
        for (int i = 0; i < 8; i++) { a += sa[i]; f += sfd[i]; }
        double pos = a / (double)K_SZ;           // sum_b mean_k exp(...)
        double neg = pos + f;
        out[0] = (float)(-log(pos / neg));
    }
}

// ---------------------------------------------------------------------------
extern "C" void kernel_launch(void* const* d_in, const int* in_sizes, int n_in,
                              void* d_out, int out_size)
{
    const float* img = (const float*)d_in[0];  // bg_img_feature [256,1024]
    const float* fg  = (const float*)d_in[1];  // fg_pro_feature [256,1024]
    const float* pro = (const float*)d_in[2];  // bg_pro_feature [256,512,1024]

    fused_kernel<<<NBLK, 256>>>(img, fg, pro, (float*)d_out);
}

// round 5
// speedup vs baseline: 1.0371x; 1.0371x over previous
#include <cuda_runtime.h>
#include <math.h>

// Problem constants (fixed by the dataset): B=256, K=512, D=1024
#define B_SZ 256
#define K_SZ 512
#define D_SZ 1024
#define INV_T (1.0f / 0.07f)

// grid = 2048: 8 blocks per sample, 8 warps per block, 8 k-rows per warp
#define BLOCKS_PER_B 8
#define K_PER_WARP 8
#define NBLK (B_SZ * BLOCKS_PER_B)   // 2048

// Scratch (no cudaMalloc allowed)
__device__ float g_fg_per_b[B_SZ];     // exp(fg_logit / T) per sample
__device__ float g_part[NBLK];         // per-block partial sums (2048 -> 8 KB)
__device__ unsigned int g_count;       // arrival counter (zero-init, self-resetting)

// ---------------------------------------------------------------------------
// Single fused kernel:
//  - per-block img-row normalization (redundant 8x/row, L2 hits)
//  - 8 warps x 8 k-rows each: stream pro from DRAM, dot vs smem img row
//  - kgrp==0 blocks also compute the fg dot
//  - LAST arriving block reduces the 2048 partials (cheap now) + writes loss
// grid = 2048, block = 256
// ---------------------------------------------------------------------------
__global__ void __launch_bounds__(256) fused_kernel(
    const float* __restrict__ img,
    const float* __restrict__ fg,
    const float* __restrict__ pro,
    float* __restrict__ out)
{
    __shared__ float4 s_img[256];   // 4 KB: the img row
    __shared__ float  s_ss[8];
    __shared__ float  s_fg[8];
    __shared__ float  s_part[8];
    __shared__ int    s_last;

    const int blk  = blockIdx.x;
    const int b    = blk >> 3;          // blk / BLOCKS_PER_B
    const int kgrp = blk & 7;           // blk % BLOCKS_PER_B
    const int t    = threadIdx.x;
    const int w    = t >> 5;
    const int l    = t & 31;

    // ---- load img row into smem + sum of squares ----
    float4 v = ((const float4*)(img + (size_t)b * D_SZ))[t];
    s_img[t] = v;

    float ss = v.x * v.x + v.y * v.y + v.z * v.z + v.w * v.w;
    #pragma unroll
    for (int o = 16; o > 0; o >>= 1)
        ss += __shfl_xor_sync(0xFFFFFFFFu, ss, o);
    if (l == 0) s_ss[w] = ss;
    __syncthreads();

    float tss = 0.f;
    #pragma unroll
    for (int i = 0; i < 8; i++) tss += s_ss[i];
    const float inv = 1.0f / sqrtf(tss);

    // ---- fg dot: only in the first block of each sample ----
    if (kgrp == 0) {
        float4 f = ((const float4*)(fg + (size_t)b * D_SZ))[t];
        float fd = v.x * f.x + v.y * f.y + v.z * f.z + v.w * f.w;
        #pragma unroll
        for (int o = 16; o > 0; o >>= 1)
            fd += __shfl_xor_sync(0xFFFFFFFFu, fd, o);
        if (l == 0) s_fg[w] = fd;
        __syncthreads();
        if (t == 0) {
            float tfd = 0.f;
            #pragma unroll
            for (int i = 0; i < 8; i++) tfd += s_fg[i];
            g_fg_per_b[b] = expf(tfd * inv * INV_T);
        }
    }

    // ---- each warp: 8 consecutive (b,k) rows streamed from DRAM ----
    const int kbase = (kgrp << 6) + (w << 3);   // kgrp*64 + w*8
    const float4* p4 = (const float4*)(pro + ((size_t)b * K_SZ + kbase) * D_SZ);

    float wsum = 0.f;
    #pragma unroll
    for (int r = 0; r < K_PER_WARP; r++) {
        const float4* row = p4 + (size_t)r * 256;   // 1024 floats = 256 float4

        float4 p[8];
        #pragma unroll
        for (int j = 0; j < 8; j++)
            p[j] = __ldcs(row + j * 32 + l);        // 8 independent LDG.128

        float acc = 0.f;
        #pragma unroll
        for (int j = 0; j < 8; j++) {
            float4 a = s_img[j * 32 + l];
            acc += a.x * p[j].x + a.y * p[j].y + a.z * p[j].z + a.w * p[j].w;
        }

        #pragma unroll
        for (int o = 16; o > 0; o >>= 1)
            acc += __shfl_xor_sync(0xFFFFFFFFu, acc, o);
        if (l == 0) wsum += expf(acc * inv * INV_T);
    }

    if (l == 0) s_part[w] = wsum;
    __syncthreads();

    // ---- publish partial, arrive at counter; detect last block ----
    if (t == 0) {
        float tsum = 0.f;
        #pragma unroll
        for (int i = 0; i < 8; i++) tsum += s_part[i];
        g_part[blk] = tsum;
        __threadfence();                          // make partial + fg visible
        unsigned r = atomicAdd(&g_count, 1u);
        s_last = (r == (unsigned)(NBLK - 1));
    }
    __syncthreads();
    if (!s_last) return;

    // =======================================================================
    // Final deterministic reduce — one block, only 2048 partials (8 KB,
    // L2-hot): 512 LDG.128 total. Fixed read order -> replay-deterministic.
    // =======================================================================
    if (t == 0) g_count = 0;                      // reset for next graph replay

    const float4* gp4 = (const float4*)g_part;    // 512 float4
    float4 x0 = gp4[t];
    float4 x1 = gp4[t + 256];
    float  fgv = g_fg_per_b[t];                   // t in [0,256)

    double acc2 = ((double)x0.x + (double)x0.y) + ((double)x0.z + (double)x0.w)
                + ((double)x1.x + (double)x1.y) + ((double)x1.z + (double)x1.w);
    double fgd  = (double)fgv;

    #pragma unroll
    for (int o = 16; o > 0; o >>= 1) {
        acc2 += __shfl_xor_sync(0xFFFFFFFFu, acc2, o);
        fgd  += __shfl_xor_sync(0xFFFFFFFFu, fgd,  o);
    }

    __shared__ double sa[8];
    __shared__ double sfd[8];
    if (l == 0) { sa[w] = acc2; sfd[w] = fgd; }
    __syncthreads();

    if (t == 0) {
        double a = 0.0, f = 0.0;
        #pragma unroll
        for (int i = 0; i < 8; i++) { a += sa[i]; f += sfd[i]; }
        double pos = a / (double)K_SZ;            // sum_b mean_k exp(...)
        double neg = pos + f;
        out[0] = (float)(-log(pos / neg));
    }
}

// ---------------------------------------------------------------------------
extern "C" void kernel_launch(void* const* d_in, const int* in_sizes, int n_in,
                              void* d_out, int out_size)
{
    const float* img = (const float*)d_in[0];  // bg_img_feature [256,1024]
    const float* fg  = (const float*)d_in[1];  // fg_pro_feature [256,1024]
    const float* pro = (const float*)d_in[2];  // bg_pro_feature [256,512,1024]

    fused_kernel<<<NBLK, 256>>>(img, fg, pro, (float*)d_out);
}